// round 6
// baseline (speedup 1.0000x reference)
#include <cuda_runtime.h>
#include <math.h>

#define N_SRC   40000
#define L_TGT   4096
#define NSPLIT  37
#define CHUNK   1082              /* ceil(40000/37); last chunk = 1048 */
#define TILE    128
#define NT      128
/* 1/(sigma*ln2), sigma=2.5 : exp(-d/sigma) = 2^(-K*d) */
#define KNEG    (-0.5770780163555852f)
#define EPSC    0.01f

typedef unsigned long long u64;

/* ---------------- packed f32x2 helpers ---------------- */
__device__ __forceinline__ u64 pk(float lo, float hi) {
    u64 r; asm("mov.b64 %0, {%1, %2};" : "=l"(r) : "f"(lo), "f"(hi)); return r;
}
__device__ __forceinline__ void upk(u64 v, float& lo, float& hi) {
    asm("mov.b64 {%0, %1}, %2;" : "=f"(lo), "=f"(hi) : "l"(v));
}
__device__ __forceinline__ u64 fma2(u64 a, u64 b, u64 c) {
    u64 d; asm("fma.rn.f32x2 %0, %1, %2, %3;" : "=l"(d) : "l"(a), "l"(b), "l"(c)); return d;
}
__device__ __forceinline__ u64 mul2(u64 a, u64 b) {
    u64 d; asm("mul.rn.f32x2 %0, %1, %2;" : "=l"(d) : "l"(a), "l"(b)); return d;
}
__device__ __forceinline__ u64 add2(u64 a, u64 b) {
    u64 d; asm("add.rn.f32x2 %0, %1, %2;" : "=l"(d) : "l"(a), "l"(b)); return d;
}
__device__ __forceinline__ float sqrt_ap(float x) {
    float r; asm("sqrt.approx.f32 %0, %1;" : "=f"(r) : "f"(x)); return r;
}
__device__ __forceinline__ float ex2_ap(float x) {
    float r; asm("ex2.approx.f32 %0, %1;" : "=f"(r) : "f"(x)); return r;
}
/* reference-matching squared norm: ((x*x + y*y) + z*z), no FMA contraction */
__device__ __forceinline__ float norm2_ref(float x, float y, float z) {
    return __fadd_rn(__fadd_rn(__fmul_rn(x, x), __fmul_rn(y, y)), __fmul_rn(z, z));
}

/* ---------------- scratch ---------------- */
__device__ ulonglong2 d_gp[N_SRC * 2];   /* argmin pairs: {(x1,x2),(y1,y2)},{(z1,z2),(n1,n2)} */
__device__ ulonglong2 d_sp[N_SRC * 2];   /* rbf pairs: raw coords + ref norm, same layout */
__device__ ulonglong2 d_fp[N_SRC * 6];   /* interleaved features (f1[k],f2[k]) */

__device__ u64   d_pbest[NSPLIT * L_TGT];
__device__ int   d_pidxL[NSPLIT * L_TGT], d_pidxR[NSPLIT * L_TGT];
__device__ u64   d_pn  [NSPLIT * L_TGT];
__device__ u64   d_pacc[NSPLIT * 12 * L_TGT];

/* ------------- prep ------------- */
__global__ void prep_kernel(const float* __restrict__ g1, const float* __restrict__ g2,
                            const float* __restrict__ s1, const float* __restrict__ s2,
                            const float* __restrict__ f1, const float* __restrict__ f2) {
    int i = blockIdx.x * blockDim.x + threadIdx.x;
    if (i >= N_SRC) return;
    float cx = g1[3*i], cy = g1[3*i+1], cz = g1[3*i+2];
    float dx = g2[3*i], dy = g2[3*i+1], dz = g2[3*i+2];
    ulonglong2 v;
    v.x = pk(cx, dx); v.y = pk(cy, dy);
    d_gp[2*i] = v;
    v.x = pk(cz, dz); v.y = pk(norm2_ref(cx, cy, cz), norm2_ref(dx, dy, dz));
    d_gp[2*i+1] = v;

    float ax = s1[3*i], ay = s1[3*i+1], az = s1[3*i+2];
    float bx = s2[3*i], by = s2[3*i+1], bz = s2[3*i+2];
    v.x = pk(ax, bx); v.y = pk(ay, by);
    d_sp[2*i] = v;
    v.x = pk(az, bz); v.y = pk(norm2_ref(ax, ay, az), norm2_ref(bx, by, bz));
    d_sp[2*i+1] = v;

#pragma unroll
    for (int m = 0; m < 6; m++) {
        v.x = pk(f1[12*i + 2*m],     f2[12*i + 2*m]);
        v.y = pk(f1[12*i + 2*m + 1], f2[12*i + 2*m + 1]);
        d_fp[6*i + m] = v;
    }
}

/* ------------- pass1: 1 target/thread, 8 blocks/SM for latency hiding ------------- */
__global__ void __launch_bounds__(NT, 8)
pass1_kernel(const float* __restrict__ locs_left, const float* __restrict__ locs_right) {
    __shared__ ulonglong2 shgp[TILE * 2];   /* 4 KB */
    __shared__ ulonglong2 shsp[TILE * 2];   /* 4 KB */
    __shared__ ulonglong2 shfp[TILE * 6];   /* 12 KB */

    const int l     = blockIdx.x * NT + threadIdx.x;
    const int split = blockIdx.y;
    const int base  = split * CHUNK;
    const int cnt   = min(CHUNK, N_SRC - base);

    float tlx = locs_left[3*l],  tly = locs_left[3*l+1],  tlz = locs_left[3*l+2];
    float trx = locs_right[3*l], tryy = locs_right[3*l+1], trz = locs_right[3*l+2];
    const u64 txp = pk(tlx, trx), typ = pk(tly, tryy), tzp = pk(tlz, trz);
    const u64 sap = pk(norm2_ref(tlx, tly, tlz), norm2_ref(trx, tryy, trz));
    const u64 NEG2P = pk(-2.0f, -2.0f);

    float bestL = 3.4e38f, bestR = 3.4e38f;
    int   bidxL = 0, bidxR = 0;
    u64 np = pk(0.f, 0.f);
    u64 acc[12];
#pragma unroll
    for (int k = 0; k < 12; k++) acc[k] = np;

    for (int t = 0; t < cnt; t += TILE) {
        const int m = min(TILE, cnt - t);
        __syncthreads();
        for (int i = threadIdx.x; i < m * 2; i += NT) {
            shgp[i] = d_gp[(base + t) * 2 + i];
            shsp[i] = d_sp[(base + t) * 2 + i];
        }
        for (int i = threadIdx.x; i < m * 6; i += NT) {
            shfp[i] = d_fp[(base + t) * 6 + i];
        }
        __syncthreads();

#pragma unroll 2
        for (int j = 0; j < m; j++) {
            const int src = base + t + j;
            /* --- argmin: bit-exact reference rounding --- */
            const ulonglong2 g0 = shgp[2*j], g1 = shgp[2*j+1];
            u64 dot = fma2(tzp, g1.x, fma2(typ, g0.y, mul2(txp, g0.x)));
            u64 sab = add2(sap, g1.y);
            u64 d2p = fma2(dot, NEG2P, sab);
            float d2L, d2R; upk(d2p, d2L, d2R);
            if (d2L < bestL) { bestL = d2L; bidxL = src; }
            if (d2R < bestR) { bestR = d2R; bidxR = src; }

            /* --- RBF weights on rbf sources: w = 2^(-K*sqrt(d2)) --- */
            const ulonglong2 s0 = shsp[2*j], s1 = shsp[2*j+1];
            u64 rdot = fma2(tzp, s1.x, fma2(typ, s0.y, mul2(txp, s0.x)));
            u64 rsab = add2(sap, s1.y);
            u64 r2p  = fma2(rdot, NEG2P, rsab);
            float r2L, r2R; upk(r2p, r2L, r2R);
            float w1 = ex2_ap(__fmul_rn(KNEG, sqrt_ap(fmaxf(r2L, 0.f))));
            float w2 = ex2_ap(__fmul_rn(KNEG, sqrt_ap(fmaxf(r2R, 0.f))));
            u64 wp = pk(w1, w2);
            np = add2(np, wp);

            /* --- packed feature accumulation: 12 fma2 --- */
#pragma unroll
            for (int q = 0; q < 6; q++) {
                const ulonglong2 f = shfp[6*j + q];
                acc[2*q]     = fma2(wp, f.x, acc[2*q]);
                acc[2*q + 1] = fma2(wp, f.y, acc[2*q + 1]);
            }
        }
    }

    const int o = split * L_TGT + l;
    d_pbest[o] = pk(bestL, bestR);
    d_pidxL[o] = bidxL; d_pidxR[o] = bidxR;
    d_pn[o] = np;
#pragma unroll
    for (int k = 0; k < 12; k++)
        d_pacc[(split * 12 + k) * L_TGT + l] = acc[k];
}

/* ------------- pass2: reduce splits, gather, normalize, MLP ------------- */
__global__ void __launch_bounds__(NT)
pass2_kernel(const float* __restrict__ g1_x, const float* __restrict__ g2_x,
             const float* __restrict__ W1, const float* __restrict__ b1,
             const float* __restrict__ W2, const float* __restrict__ b2,
             float* __restrict__ out) {
    __shared__ float sW1[2500], sb1[50], sW2[50];
    for (int i = threadIdx.x; i < 2500; i += NT) sW1[i] = W1[i];
    if (threadIdx.x < 50) { sb1[threadIdx.x] = b1[threadIdx.x]; sW2[threadIdx.x] = W2[threadIdx.x]; }
    __syncthreads();

    const int l = blockIdx.x * NT + threadIdx.x;

    float bestL = 3.4e38f, bestR = 3.4e38f;
    int bidxL = 0, bidxR = 0;
    u64 np = pk(EPSC, EPSC);
    u64 acc[12];
#pragma unroll
    for (int k = 0; k < 12; k++) acc[k] = pk(0.f, 0.f);

    for (int s = 0; s < NSPLIT; s++) {
        int o = s * L_TGT + l;
        float bL, bR; upk(d_pbest[o], bL, bR);
        if (bL < bestL) { bestL = bL; bidxL = d_pidxL[o]; }
        if (bR < bestR) { bestR = bR; bidxR = d_pidxR[o]; }
        np = add2(np, d_pn[o]);
#pragma unroll
        for (int k = 0; k < 12; k++)
            acc[k] = add2(acc[k], d_pacc[(s * 12 + k) * L_TGT + l]);
    }

    float nL, nR; upk(np, nL, nR);
    float x[50];
    const float* gl = &g1_x[bidxL * 12];
    const float* gr = &g2_x[bidxR * 12];
#pragma unroll
    for (int k = 0; k < 12; k++) x[k] = gl[k];
#pragma unroll
    for (int k = 0; k < 12; k++) x[25 + k] = gr[k];
    float invL = 1.f / nL, invR = 1.f / nR;
#pragma unroll
    for (int k = 0; k < 12; k++) {
        float aLk, aRk; upk(acc[k], aLk, aRk);
        x[12 + k] = aLk * invL;
        x[37 + k] = aRk * invR;
    }
    x[24] = tanhf(nL);
    x[49] = tanhf(nR);

    float outv = b2[0];
    for (int j = 0; j < 50; j++) {
        float h = sb1[j];
#pragma unroll
        for (int i = 0; i < 50; i++) h = fmaf(x[i], sW1[i * 50 + j], h);
        outv = fmaf(fmaxf(h, 0.f), sW2[j], outv);
    }
    out[l] = outv;
}

extern "C" void kernel_launch(void* const* d_in, const int* in_sizes, int n_in,
                              void* d_out, int out_size) {
    const float* locs_left  = (const float*)d_in[0];
    const float* locs_right = (const float*)d_in[1];
    const float* g1_pos     = (const float*)d_in[2];
    const float* g1_x       = (const float*)d_in[3];
    const float* g2_pos     = (const float*)d_in[4];
    const float* g2_x       = (const float*)d_in[5];
    const float* s1_verts   = (const float*)d_in[6];
    const float* s1_x       = (const float*)d_in[7];
    const float* s2_verts   = (const float*)d_in[8];
    const float* s2_x       = (const float*)d_in[9];
    const float* W1         = (const float*)d_in[10];
    const float* b1         = (const float*)d_in[11];
    const float* W2         = (const float*)d_in[12];
    const float* b2         = (const float*)d_in[13];
    float* out = (float*)d_out;

    prep_kernel<<<(N_SRC + NT - 1) / NT, NT>>>(g1_pos, g2_pos, s1_verts, s2_verts, s1_x, s2_x);
    dim3 grid1(L_TGT / NT, NSPLIT);   /* 32 x 37 = 1184 blocks = 148 SMs * occ 8 */
    pass1_kernel<<<grid1, NT>>>(locs_left, locs_right);
    pass2_kernel<<<L_TGT / NT, NT>>>(g1_x, g2_x, W1, b1, W2, b2, out);
}

// round 7
// speedup vs baseline: 1.3265x; 1.3265x over previous
#include <cuda_runtime.h>
#include <math.h>

#define N_SRC   40000
#define L_TGT   4096
#define NSPLIT  37
#define CHUNK   1082              /* ceil(40000/37); last chunk = 1048 */
#define TILE    200
#define NT      128
#define TPT     2                 /* targets per thread */
/* 1/(sigma*ln2), sigma=2.5 : exp(-d/sigma) = 2^(-K*d) */
#define KNEG    (-0.5770780163555852f)
#define EPSC    0.01f

typedef unsigned long long u64;

/* ---------------- packed f32x2 helpers ---------------- */
__device__ __forceinline__ u64 pk(float lo, float hi) {
    u64 r; asm("mov.b64 %0, {%1, %2};" : "=l"(r) : "f"(lo), "f"(hi)); return r;
}
__device__ __forceinline__ void upk(u64 v, float& lo, float& hi) {
    asm("mov.b64 {%0, %1}, %2;" : "=f"(lo), "=f"(hi) : "l"(v));
}
__device__ __forceinline__ u64 fma2(u64 a, u64 b, u64 c) {
    u64 d; asm("fma.rn.f32x2 %0, %1, %2, %3;" : "=l"(d) : "l"(a), "l"(b), "l"(c)); return d;
}
__device__ __forceinline__ u64 mul2(u64 a, u64 b) {
    u64 d; asm("mul.rn.f32x2 %0, %1, %2;" : "=l"(d) : "l"(a), "l"(b)); return d;
}
__device__ __forceinline__ u64 add2(u64 a, u64 b) {
    u64 d; asm("add.rn.f32x2 %0, %1, %2;" : "=l"(d) : "l"(a), "l"(b)); return d;
}
__device__ __forceinline__ float sqrt_ap(float x) {
    float r; asm("sqrt.approx.f32 %0, %1;" : "=f"(r) : "f"(x)); return r;
}
__device__ __forceinline__ float ex2_ap(float x) {
    float r; asm("ex2.approx.f32 %0, %1;" : "=f"(r) : "f"(x)); return r;
}
/* reference-matching squared norm: ((x*x + y*y) + z*z), no FMA contraction */
__device__ __forceinline__ float norm2_ref(float x, float y, float z) {
    return __fadd_rn(__fadd_rn(__fmul_rn(x, x), __fmul_rn(y, y)), __fmul_rn(z, z));
}

/* ---------------- scratch (partials only; packing now in-kernel) ---------------- */
__device__ u64   d_pbest[NSPLIT * L_TGT];
__device__ int   d_pidxL[NSPLIT * L_TGT], d_pidxR[NSPLIT * L_TGT];
__device__ u64   d_pn  [NSPLIT * L_TGT];
__device__ u64   d_pacc[NSPLIT * 12 * L_TGT];

/* ------------- pass1: fill-from-raw + 2 targets/thread packed inner loop ------------- */
__global__ void __launch_bounds__(NT, 4)
pass1_kernel(const float* __restrict__ locs_left, const float* __restrict__ locs_right,
             const float* __restrict__ g1_pos, const float* __restrict__ g2_pos,
             const float* __restrict__ s1_verts, const float* __restrict__ s2_verts,
             const float* __restrict__ s1_x, const float* __restrict__ s2_x) {
    __shared__ ulonglong2 shgp[TILE * 2];   /* argmin src pairs: {(x,x),(y,y)},{(z,z),(n,n)} */
    __shared__ ulonglong2 shsp[TILE * 2];   /* rbf src pairs, same layout */
    __shared__ ulonglong2 shfp[TILE * 6];   /* interleaved features (f1[k],f2[k]) */

    const int l0    = blockIdx.x * (NT * TPT) + threadIdx.x;
    const int l1    = l0 + NT;
    const int split = blockIdx.y;
    const int base  = split * CHUNK;
    const int cnt   = min(CHUNK, N_SRC - base);

    /* per-target packed constants — target side shared by argmin & rbf */
    u64 txp[TPT], typ[TPT], tzp[TPT], sap[TPT];
    {
        const int ls[TPT] = { l0, l1 };
#pragma unroll
        for (int u = 0; u < TPT; u++) {
            int l = ls[u];
            float tlx = locs_left[3*l],  tly = locs_left[3*l+1],  tlz = locs_left[3*l+2];
            float trx = locs_right[3*l], tryy = locs_right[3*l+1], trz = locs_right[3*l+2];
            txp[u] = pk(tlx, trx); typ[u] = pk(tly, tryy); tzp[u] = pk(tlz, trz);
            sap[u] = pk(norm2_ref(tlx, tly, tlz), norm2_ref(trx, tryy, trz));
        }
    }
    const u64 NEG2P = pk(-2.0f, -2.0f);

    float bestL[TPT], bestR[TPT];
    int   bidxL[TPT], bidxR[TPT];
    u64 np[TPT];
    u64 acc[TPT][12];
#pragma unroll
    for (int u = 0; u < TPT; u++) {
        bestL[u] = 3.4e38f; bestR[u] = 3.4e38f;
        bidxL[u] = 0; bidxR[u] = 0;
        np[u] = pk(0.f, 0.f);
#pragma unroll
        for (int k = 0; k < 12; k++) acc[u][k] = np[u];
    }

    for (int t = 0; t < cnt; t += TILE) {
        const int m = min(TILE, cnt - t);
        __syncthreads();
        /* ---- fill: read raw globals, pack (incl. reference-rounded norms) ---- */
        for (int i = threadIdx.x; i < m; i += NT) {
            const int idx = base + t + i;
            float cx = g1_pos[3*idx], cy = g1_pos[3*idx+1], cz = g1_pos[3*idx+2];
            float dx = g2_pos[3*idx], dy = g2_pos[3*idx+1], dz = g2_pos[3*idx+2];
            ulonglong2 v;
            v.x = pk(cx, dx); v.y = pk(cy, dy);
            shgp[2*i] = v;
            v.x = pk(cz, dz); v.y = pk(norm2_ref(cx, cy, cz), norm2_ref(dx, dy, dz));
            shgp[2*i+1] = v;

            float ax = s1_verts[3*idx], ay = s1_verts[3*idx+1], az = s1_verts[3*idx+2];
            float bx = s2_verts[3*idx], by = s2_verts[3*idx+1], bz = s2_verts[3*idx+2];
            v.x = pk(ax, bx); v.y = pk(ay, by);
            shsp[2*i] = v;
            v.x = pk(az, bz); v.y = pk(norm2_ref(ax, ay, az), norm2_ref(bx, by, bz));
            shsp[2*i+1] = v;

            const float4* f1v = (const float4*)(s1_x + 12 * idx);   /* 48B rows, 16B aligned */
            const float4* f2v = (const float4*)(s2_x + 12 * idx);
#pragma unroll
            for (int q = 0; q < 3; q++) {
                float4 a = f1v[q], b = f2v[q];
                ulonglong2 w0, w1;
                w0.x = pk(a.x, b.x); w0.y = pk(a.y, b.y);
                w1.x = pk(a.z, b.z); w1.y = pk(a.w, b.w);
                shfp[6*i + 2*q]     = w0;
                shfp[6*i + 2*q + 1] = w1;
            }
        }
        __syncthreads();

#pragma unroll 2
        for (int j = 0; j < m; j++) {
            const int src = base + t + j;
            const ulonglong2 g0 = shgp[2*j], g1 = shgp[2*j+1];
            const ulonglong2 s0 = shsp[2*j], s1 = shsp[2*j+1];

            u64 wp[TPT];
#pragma unroll
            for (int u = 0; u < TPT; u++) {
                /* --- argmin distance (bit-exact reference rounding) --- */
                u64 dot = fma2(tzp[u], g1.x, fma2(typ[u], g0.y, mul2(txp[u], g0.x)));
                u64 sab = add2(sap[u], g1.y);
                u64 d2p = fma2(dot, NEG2P, sab);
                float d2L, d2R; upk(d2p, d2L, d2R);
                if (d2L < bestL[u]) { bestL[u] = d2L; bidxL[u] = src; }
                if (d2R < bestR[u]) { bestR[u] = d2R; bidxR[u] = src; }

                /* --- rbf distance (same target constants) --- */
                u64 rdot = fma2(tzp[u], s1.x, fma2(typ[u], s0.y, mul2(txp[u], s0.x)));
                u64 rsab = add2(sap[u], s1.y);
                u64 r2p  = fma2(rdot, NEG2P, rsab);
                float r2L, r2R; upk(r2p, r2L, r2R);
                /* w = 2^(K*-sqrt(d2)) == exp(-d/sigma) */
                float w1 = ex2_ap(__fmul_rn(KNEG, sqrt_ap(fmaxf(r2L, 0.f))));
                float w2 = ex2_ap(__fmul_rn(KNEG, sqrt_ap(fmaxf(r2R, 0.f))));
                wp[u] = pk(w1, w2);
                np[u] = add2(np[u], wp[u]);
            }

            /* --- packed feature accumulation, features shared across targets --- */
#pragma unroll
            for (int q = 0; q < 6; q++) {
                const ulonglong2 f = shfp[6*j + q];
#pragma unroll
                for (int u = 0; u < TPT; u++) {
                    acc[u][2*q]     = fma2(wp[u], f.x, acc[u][2*q]);
                    acc[u][2*q + 1] = fma2(wp[u], f.y, acc[u][2*q + 1]);
                }
            }
        }
    }

    const int ls[TPT] = { l0, l1 };
#pragma unroll
    for (int u = 0; u < TPT; u++) {
        const int o = split * L_TGT + ls[u];
        d_pbest[o] = pk(bestL[u], bestR[u]);
        d_pidxL[o] = bidxL[u]; d_pidxR[o] = bidxR[u];
        d_pn[o] = np[u];
#pragma unroll
        for (int k = 0; k < 12; k++)
            d_pacc[(split * 12 + k) * L_TGT + ls[u]] = acc[u][k];
    }
}

/* ------------- pass2: reduce splits, gather, normalize, MLP ------------- */
__global__ void __launch_bounds__(NT)
pass2_kernel(const float* __restrict__ g1_x, const float* __restrict__ g2_x,
             const float* __restrict__ W1, const float* __restrict__ b1,
             const float* __restrict__ W2, const float* __restrict__ b2,
             float* __restrict__ out) {
    __shared__ float sW1[2500], sb1[50], sW2[50];
    for (int i = threadIdx.x; i < 2500; i += NT) sW1[i] = W1[i];
    if (threadIdx.x < 50) { sb1[threadIdx.x] = b1[threadIdx.x]; sW2[threadIdx.x] = W2[threadIdx.x]; }
    __syncthreads();

    const int l = blockIdx.x * NT + threadIdx.x;

    float bestL = 3.4e38f, bestR = 3.4e38f;
    int bidxL = 0, bidxR = 0;
    u64 np = pk(EPSC, EPSC);
    u64 acc[12];
#pragma unroll
    for (int k = 0; k < 12; k++) acc[k] = pk(0.f, 0.f);

    for (int s = 0; s < NSPLIT; s++) {
        int o = s * L_TGT + l;
        float bL, bR; upk(d_pbest[o], bL, bR);
        if (bL < bestL) { bestL = bL; bidxL = d_pidxL[o]; }
        if (bR < bestR) { bestR = bR; bidxR = d_pidxR[o]; }
        np = add2(np, d_pn[o]);
#pragma unroll
        for (int k = 0; k < 12; k++)
            acc[k] = add2(acc[k], d_pacc[(s * 12 + k) * L_TGT + l]);
    }

    float nL, nR; upk(np, nL, nR);
    float x[50];
    const float* gl = &g1_x[bidxL * 12];
    const float* gr = &g2_x[bidxR * 12];
#pragma unroll
    for (int k = 0; k < 12; k++) x[k] = gl[k];
#pragma unroll
    for (int k = 0; k < 12; k++) x[25 + k] = gr[k];
    float invL = 1.f / nL, invR = 1.f / nR;
#pragma unroll
    for (int k = 0; k < 12; k++) {
        float aLk, aRk; upk(acc[k], aLk, aRk);
        x[12 + k] = aLk * invL;
        x[37 + k] = aRk * invR;
    }
    x[24] = tanhf(nL);
    x[49] = tanhf(nR);

    float outv = b2[0];
    for (int j = 0; j < 50; j++) {
        float h = sb1[j];
#pragma unroll
        for (int i = 0; i < 50; i++) h = fmaf(x[i], sW1[i * 50 + j], h);
        outv = fmaf(fmaxf(h, 0.f), sW2[j], outv);
    }
    out[l] = outv;
}

extern "C" void kernel_launch(void* const* d_in, const int* in_sizes, int n_in,
                              void* d_out, int out_size) {
    const float* locs_left  = (const float*)d_in[0];
    const float* locs_right = (const float*)d_in[1];
    const float* g1_pos     = (const float*)d_in[2];
    const float* g1_x       = (const float*)d_in[3];
    const float* g2_pos     = (const float*)d_in[4];
    const float* g2_x       = (const float*)d_in[5];
    const float* s1_verts   = (const float*)d_in[6];
    const float* s1_x       = (const float*)d_in[7];
    const float* s2_verts   = (const float*)d_in[8];
    const float* s2_x       = (const float*)d_in[9];
    const float* W1         = (const float*)d_in[10];
    const float* b1         = (const float*)d_in[11];
    const float* W2         = (const float*)d_in[12];
    const float* b2         = (const float*)d_in[13];
    float* out = (float*)d_out;

    dim3 grid1(L_TGT / (NT * TPT), NSPLIT);   /* 16 x 37 = 592 = 148 SMs * occ 4 */
    pass1_kernel<<<grid1, NT>>>(locs_left, locs_right, g1_pos, g2_pos,
                                s1_verts, s2_verts, s1_x, s2_x);
    pass2_kernel<<<L_TGT / NT, NT>>>(g1_x, g2_x, W1, b1, W2, b2, out);
}

// round 8
// speedup vs baseline: 1.3506x; 1.0182x over previous
#include <cuda_runtime.h>
#include <math.h>

#define N_SRC   40000
#define L_TGT   4096
#define NSPLIT  37
#define CHUNK   1082              /* ceil(40000/37); last chunk = 1048 */
#define TILE    200
#define NT      128
#define TPT     4                 /* targets per thread */
#define TGB     (NT * TPT)        /* 512 targets per block */
/* 1/(sigma*ln2), sigma=2.5 : exp(-d/sigma) = 2^(-K*d) */
#define KNEG    (-0.5770780163555852f)
#define EPSC    0.01f

typedef unsigned long long u64;

/* ---------------- packed f32x2 helpers ---------------- */
__device__ __forceinline__ u64 pk(float lo, float hi) {
    u64 r; asm("mov.b64 %0, {%1, %2};" : "=l"(r) : "f"(lo), "f"(hi)); return r;
}
__device__ __forceinline__ void upk(u64 v, float& lo, float& hi) {
    asm("mov.b64 {%0, %1}, %2;" : "=f"(lo), "=f"(hi) : "l"(v));
}
__device__ __forceinline__ u64 fma2(u64 a, u64 b, u64 c) {
    u64 d; asm("fma.rn.f32x2 %0, %1, %2, %3;" : "=l"(d) : "l"(a), "l"(b), "l"(c)); return d;
}
__device__ __forceinline__ u64 mul2(u64 a, u64 b) {
    u64 d; asm("mul.rn.f32x2 %0, %1, %2;" : "=l"(d) : "l"(a), "l"(b)); return d;
}
__device__ __forceinline__ u64 add2(u64 a, u64 b) {
    u64 d; asm("add.rn.f32x2 %0, %1, %2;" : "=l"(d) : "l"(a), "l"(b)); return d;
}
__device__ __forceinline__ float sqrt_ap(float x) {
    float r; asm("sqrt.approx.f32 %0, %1;" : "=f"(r) : "f"(x)); return r;
}
__device__ __forceinline__ float ex2_ap(float x) {
    float r; asm("ex2.approx.f32 %0, %1;" : "=f"(r) : "f"(x)); return r;
}
/* reference-matching squared norm: ((x*x + y*y) + z*z), no FMA contraction */
__device__ __forceinline__ float norm2_ref(float x, float y, float z) {
    return __fadd_rn(__fadd_rn(__fmul_rn(x, x), __fmul_rn(y, y)), __fmul_rn(z, z));
}

/* ---------------- scratch ---------------- */
__device__ u64   d_pbest[NSPLIT * L_TGT];
__device__ int   d_pidxL[NSPLIT * L_TGT], d_pidxR[NSPLIT * L_TGT];
__device__ u64   d_pn  [NSPLIT * L_TGT];
__device__ u64   d_pacc[NSPLIT * 12 * L_TGT];

/* ------------- pass1: fill-from-raw + 4 targets/thread packed inner loop ------------- */
__global__ void __launch_bounds__(NT, 2)
pass1_kernel(const float* __restrict__ locs_left, const float* __restrict__ locs_right,
             const float* __restrict__ g1_pos, const float* __restrict__ g2_pos,
             const float* __restrict__ s1_verts, const float* __restrict__ s2_verts,
             const float* __restrict__ s1_x, const float* __restrict__ s2_x) {
    __shared__ ulonglong2 shgp[TILE * 2];   /* 6.4 KB */
    __shared__ ulonglong2 shsp[TILE * 2];   /* 6.4 KB */
    __shared__ ulonglong2 shfp[TILE * 6];   /* 19.2 KB */

    const int split = blockIdx.y;
    const int base  = split * CHUNK;
    const int cnt   = min(CHUNK, N_SRC - base);

    u64 txp[TPT], typ[TPT], tzp[TPT], sap[TPT];
#pragma unroll
    for (int u = 0; u < TPT; u++) {
        int l = blockIdx.x * TGB + threadIdx.x + u * NT;
        float tlx = locs_left[3*l],  tly = locs_left[3*l+1],  tlz = locs_left[3*l+2];
        float trx = locs_right[3*l], tryy = locs_right[3*l+1], trz = locs_right[3*l+2];
        txp[u] = pk(tlx, trx); typ[u] = pk(tly, tryy); tzp[u] = pk(tlz, trz);
        sap[u] = pk(norm2_ref(tlx, tly, tlz), norm2_ref(trx, tryy, trz));
    }
    const u64 NEG2P = pk(-2.0f, -2.0f);

    float bestL[TPT], bestR[TPT];
    int   bidxL[TPT], bidxR[TPT];
    u64 np[TPT];
    u64 acc[TPT][12];
#pragma unroll
    for (int u = 0; u < TPT; u++) {
        bestL[u] = 3.4e38f; bestR[u] = 3.4e38f;
        bidxL[u] = 0; bidxR[u] = 0;
        np[u] = pk(0.f, 0.f);
#pragma unroll
        for (int k = 0; k < 12; k++) acc[u][k] = np[u];
    }

    for (int t = 0; t < cnt; t += TILE) {
        const int m = min(TILE, cnt - t);
        __syncthreads();
        for (int i = threadIdx.x; i < m; i += NT) {
            const int idx = base + t + i;
            float cx = g1_pos[3*idx], cy = g1_pos[3*idx+1], cz = g1_pos[3*idx+2];
            float dx = g2_pos[3*idx], dy = g2_pos[3*idx+1], dz = g2_pos[3*idx+2];
            ulonglong2 v;
            v.x = pk(cx, dx); v.y = pk(cy, dy);
            shgp[2*i] = v;
            v.x = pk(cz, dz); v.y = pk(norm2_ref(cx, cy, cz), norm2_ref(dx, dy, dz));
            shgp[2*i+1] = v;

            float ax = s1_verts[3*idx], ay = s1_verts[3*idx+1], az = s1_verts[3*idx+2];
            float bx = s2_verts[3*idx], by = s2_verts[3*idx+1], bz = s2_verts[3*idx+2];
            v.x = pk(ax, bx); v.y = pk(ay, by);
            shsp[2*i] = v;
            v.x = pk(az, bz); v.y = pk(norm2_ref(ax, ay, az), norm2_ref(bx, by, bz));
            shsp[2*i+1] = v;

            const float4* f1v = (const float4*)(s1_x + 12 * idx);
            const float4* f2v = (const float4*)(s2_x + 12 * idx);
#pragma unroll
            for (int q = 0; q < 3; q++) {
                float4 a = f1v[q], b = f2v[q];
                ulonglong2 w0, w1;
                w0.x = pk(a.x, b.x); w0.y = pk(a.y, b.y);
                w1.x = pk(a.z, b.z); w1.y = pk(a.w, b.w);
                shfp[6*i + 2*q]     = w0;
                shfp[6*i + 2*q + 1] = w1;
            }
        }
        __syncthreads();

#pragma unroll 1
        for (int j = 0; j < m; j++) {
            const int src = base + t + j;
            const ulonglong2 g0 = shgp[2*j], g1 = shgp[2*j+1];
            const ulonglong2 s0 = shsp[2*j], s1 = shsp[2*j+1];

            u64 wp[TPT];
#pragma unroll
            for (int u = 0; u < TPT; u++) {
                /* --- argmin distance (bit-exact reference rounding) --- */
                u64 dot = fma2(tzp[u], g1.x, fma2(typ[u], g0.y, mul2(txp[u], g0.x)));
                u64 sab = add2(sap[u], g1.y);
                u64 d2p = fma2(dot, NEG2P, sab);
                float d2L, d2R; upk(d2p, d2L, d2R);
                if (d2L < bestL[u]) { bestL[u] = d2L; bidxL[u] = src; }
                if (d2R < bestR[u]) { bestR[u] = d2R; bidxR[u] = src; }

                /* --- rbf distance (same target constants) --- */
                u64 rdot = fma2(tzp[u], s1.x, fma2(typ[u], s0.y, mul2(txp[u], s0.x)));
                u64 rsab = add2(sap[u], s1.y);
                u64 r2p  = fma2(rdot, NEG2P, rsab);
                float r2L, r2R; upk(r2p, r2L, r2R);
                float w1 = ex2_ap(__fmul_rn(KNEG, sqrt_ap(fmaxf(r2L, 0.f))));
                float w2 = ex2_ap(__fmul_rn(KNEG, sqrt_ap(fmaxf(r2R, 0.f))));
                wp[u] = pk(w1, w2);
                np[u] = add2(np[u], wp[u]);
            }

#pragma unroll
            for (int q = 0; q < 6; q++) {
                const ulonglong2 f = shfp[6*j + q];
#pragma unroll
                for (int u = 0; u < TPT; u++) {
                    acc[u][2*q]     = fma2(wp[u], f.x, acc[u][2*q]);
                    acc[u][2*q + 1] = fma2(wp[u], f.y, acc[u][2*q + 1]);
                }
            }
        }
    }

#pragma unroll
    for (int u = 0; u < TPT; u++) {
        const int l = blockIdx.x * TGB + threadIdx.x + u * NT;
        const int o = split * L_TGT + l;
        d_pbest[o] = pk(bestL[u], bestR[u]);
        d_pidxL[o] = bidxL[u]; d_pidxR[o] = bidxR[u];
        d_pn[o] = np[u];
#pragma unroll
        for (int k = 0; k < 12; k++)
            d_pacc[(split * 12 + k) * L_TGT + l] = acc[u][k];
    }
}

/* ------------- pass2: warp per row — parallel reduce + parallel MLP ------------- */
#define P2NT 128
__global__ void __launch_bounds__(P2NT)
pass2_kernel(const float* __restrict__ g1_x, const float* __restrict__ g2_x,
             const float* __restrict__ W1, const float* __restrict__ b1,
             const float* __restrict__ W2, const float* __restrict__ b2,
             float* __restrict__ out) {
    __shared__ float sW1[2500], sb1[50], sW2[50];
    __shared__ float sx[P2NT / 32][52];
    for (int i = threadIdx.x; i < 2500; i += P2NT) sW1[i] = W1[i];
    if (threadIdx.x < 50) { sb1[threadIdx.x] = b1[threadIdx.x]; sW2[threadIdx.x] = W2[threadIdx.x]; }
    __syncthreads();

    const int w    = threadIdx.x >> 5;
    const int lane = threadIdx.x & 31;
    const int row  = blockIdx.x * (P2NT / 32) + w;

    /* ---- lane-parallel split reduction: lane handles s=lane (and s=lane+32 if <NSPLIT) ---- */
    float bestL = 3.4e38f, bestR = 3.4e38f;
    int bidxL = 0, bidxR = 0;
    float nL = 0.f, nR = 0.f;
    float aL[12], aR[12];
#pragma unroll
    for (int k = 0; k < 12; k++) { aL[k] = 0.f; aR[k] = 0.f; }

#pragma unroll
    for (int half = 0; half < 2; half++) {
        int s = lane + half * 32;
        if (s < NSPLIT) {
            int o = s * L_TGT + row;
            float bL, bR; upk(d_pbest[o], bL, bR);
            if (bL < bestL) { bestL = bL; bidxL = d_pidxL[o]; }
            if (bR < bestR) { bestR = bR; bidxR = d_pidxR[o]; }
            float pnL, pnR; upk(d_pn[o], pnL, pnR);
            nL += pnL; nR += pnR;
#pragma unroll
            for (int k = 0; k < 12; k++) {
                float xk, yk; upk(d_pacc[(s * 12 + k) * L_TGT + row], xk, yk);
                aL[k] += xk; aR[k] += yk;
            }
        }
    }

    /* ---- warp butterfly reduce ---- */
#pragma unroll
    for (int m = 16; m >= 1; m >>= 1) {
        float obL = __shfl_xor_sync(0xffffffffu, bestL, m);
        int   oiL = __shfl_xor_sync(0xffffffffu, bidxL, m);
        if (obL < bestL || (obL == bestL && oiL < bidxL)) { bestL = obL; bidxL = oiL; }
        float obR = __shfl_xor_sync(0xffffffffu, bestR, m);
        int   oiR = __shfl_xor_sync(0xffffffffu, bidxR, m);
        if (obR < bestR || (obR == bestR && oiR < bidxR)) { bestR = obR; bidxR = oiR; }
        nL += __shfl_xor_sync(0xffffffffu, nL, m);
        nR += __shfl_xor_sync(0xffffffffu, nR, m);
#pragma unroll
        for (int k = 0; k < 12; k++) {
            aL[k] += __shfl_xor_sync(0xffffffffu, aL[k], m);
            aR[k] += __shfl_xor_sync(0xffffffffu, aR[k], m);
        }
    }
    nL += EPSC; nR += EPSC;

    /* ---- lane 0 assembles x[50] in smem (static register indexing) ---- */
    if (lane == 0) {
        const float* gl = &g1_x[bidxL * 12];
        const float* gr = &g2_x[bidxR * 12];
        float invL = 1.f / nL, invR = 1.f / nR;
#pragma unroll
        for (int k = 0; k < 12; k++) {
            sx[w][k]      = gl[k];
            sx[w][12 + k] = aL[k] * invL;
            sx[w][25 + k] = gr[k];
            sx[w][37 + k] = aR[k] * invR;
        }
        sx[w][24] = tanhf(nL);
        sx[w][49] = tanhf(nR);
    }
    __syncwarp();

    /* ---- parallel MLP: lane j computes neuron j (and j+32 when lane<18) ---- */
    const int j1 = lane;
    const int j2 = lane + 32;
    float h1 = sb1[j1];
    float h2 = (j2 < 50) ? sb1[j2] : 0.f;
#pragma unroll 10
    for (int i = 0; i < 50; i++) {
        float xi = sx[w][i];
        h1 = fmaf(xi, sW1[i * 50 + j1], h1);
        if (j2 < 50) h2 = fmaf(xi, sW1[i * 50 + j2], h2);
    }
    float val = (j1 < 50 ? fmaxf(h1, 0.f) * sW2[j1] : 0.f)
              + (j2 < 50 ? fmaxf(h2, 0.f) * sW2[j2] : 0.f);
#pragma unroll
    for (int m = 16; m >= 1; m >>= 1)
        val += __shfl_xor_sync(0xffffffffu, val, m);
    if (lane == 0) out[row] = val + b2[0];
}

extern "C" void kernel_launch(void* const* d_in, const int* in_sizes, int n_in,
                              void* d_out, int out_size) {
    const float* locs_left  = (const float*)d_in[0];
    const float* locs_right = (const float*)d_in[1];
    const float* g1_pos     = (const float*)d_in[2];
    const float* g1_x       = (const float*)d_in[3];
    const float* g2_pos     = (const float*)d_in[4];
    const float* g2_x       = (const float*)d_in[5];
    const float* s1_verts   = (const float*)d_in[6];
    const float* s1_x       = (const float*)d_in[7];
    const float* s2_verts   = (const float*)d_in[8];
    const float* s2_x       = (const float*)d_in[9];
    const float* W1         = (const float*)d_in[10];
    const float* b1         = (const float*)d_in[11];
    const float* W2         = (const float*)d_in[12];
    const float* b2         = (const float*)d_in[13];
    float* out = (float*)d_out;

    dim3 grid1(L_TGT / TGB, NSPLIT);   /* 8 x 37 = 296 = 148 SMs * occ 2 */
    pass1_kernel<<<grid1, NT>>>(locs_left, locs_right, g1_pos, g2_pos,
                                s1_verts, s2_verts, s1_x, s2_x);
    pass2_kernel<<<L_TGT / (P2NT / 32), P2NT>>>(g1_x, g2_x, W1, b1, W2, b2, out);
}